// round 2
// baseline (speedup 1.0000x reference)
#include <cuda_runtime.h>
#include <cuda_bf16.h>

// Problem constants
#define B_DIM 8
#define C_DIM 64
#define T_DIM 128
#define N_DIM 207
#define TN    (T_DIM * N_DIM)   // 26496 pixels per (b, channel)
#define JT_BLK 96               // kernel A: pixels per block tile (26496 = 96*276)
#define NBLK_J (TN / JT_BLK)    // 276

// Scratch for projected Q, K, V (fp32). Static __device__ array per harness rules.
__device__ float g_proj[3][(size_t)B_DIM * C_DIM * TN];

// ---------------- helpers ----------------
__device__ __forceinline__ unsigned short bf16_bits(__nv_bfloat16 h) {
    return *reinterpret_cast<unsigned short*>(&h);
}

// Split fp32 into hi/lo bf16 (3-term MMA gives ~2^-16 relative error)
__device__ __forceinline__ void split2(float x, unsigned short& h, unsigned short& l) {
    __nv_bfloat16 hb = __float2bfloat16(x);
    float r = x - __bfloat162float(hb);
    __nv_bfloat16 lb = __float2bfloat16(r);
    h = bf16_bits(hb);
    l = bf16_bits(lb);
}

// Swizzled half-index into the transposed X tile Xs[j][c]:
//  - row stride 72 halves (36 words): word bank gets 4*j term
//  - XOR on c bits [1:2] keyed by j bits [3:4]
// => conflict-free for both transposed 16-bit stores (lanes = consecutive j)
//    and m16n8k16 A-fragment loads (lanes = (j=lane/4, c=2*(lane%4))).
__device__ __forceinline__ int xs_idx(int j, int c) {
    return j * 72 + (c ^ (((j >> 3) & 3) << 1));
}

__device__ __forceinline__ void mma_bf16(float* d, const unsigned* a, const unsigned* b) {
    asm volatile(
        "mma.sync.aligned.m16n8k16.row.col.f32.bf16.bf16.f32 "
        "{%0,%1,%2,%3},{%4,%5,%6,%7},{%8,%9},{%0,%1,%2,%3};\n"
        : "+f"(d[0]), "+f"(d[1]), "+f"(d[2]), "+f"(d[3])
        : "r"(a[0]), "r"(a[1]), "r"(a[2]), "r"(a[3]),
          "r"(b[0]), "r"(b[1]));
}

// ---------------- Kernel A: projections via split-bf16 tensor cores ----------------
// grid = (276 j-tiles, 8 batches, 3 projections), 192 threads (6 warps).
// Block computes Y[96 j][64 o] = X[64 c][96 j]^T * W[64 o][64 c]^T + bias
// MMA mapping: m-axis = j, n-axis = o, k-axis = c.
//   A[j][c] = transposed X tile in SMEM (swizzled),
//   B (col-major K x N) fragment == W[o][c] rows, native layout.
__global__ __launch_bounds__(192) void proj_kernel(
    const float* __restrict__ q, const float* __restrict__ k, const float* __restrict__ v,
    const float* __restrict__ Wq, const float* __restrict__ bq,
    const float* __restrict__ Wk, const float* __restrict__ bk,
    const float* __restrict__ Wv, const float* __restrict__ bv)
{
    __shared__ unsigned short Xh[JT_BLK * 72], Xl[JT_BLK * 72];
    __shared__ unsigned short Wh[64 * 72], Wl[64 * 72];
    __shared__ float bias_s[64];

    const int z = blockIdx.z;
    const float* __restrict__ X = (z == 0) ? q : (z == 1) ? k : v;
    const float* __restrict__ W = (z == 0) ? Wq : (z == 1) ? Wk : Wv;
    const float* __restrict__ bb = (z == 0) ? bq : (z == 1) ? bk : bv;
    float* __restrict__ O = g_proj[z];

    const int b   = blockIdx.y;
    const long j0 = (long)blockIdx.x * JT_BLK;
    const int tid = threadIdx.x;

    // Load weight matrix, split into hi/lo bf16. Row stride 72 (pad) -> the
    // B-fragment reads (o=lane/4, c=k0+2*(lane%4)) are conflict-free.
    for (int idx = tid; idx < 64 * 64; idx += 192) {
        int o = idx >> 6, c = idx & 63;
        unsigned short h, l;
        split2(W[idx], h, l);
        Wh[o * 72 + c] = h;
        Wl[o * 72 + c] = l;
    }
    if (tid < 64) bias_s[tid] = bb[tid];

    // Load X tile [64 c][96 j], transpose into Xs[j][c] (split hi/lo).
    // Scalar loads so warp lanes map to consecutive j -> coalesced LDG (128B)
    // and conflict-free swizzled STS.16.
    {
        const int jl  = tid % JT_BLK;       // 0..95
        const int cst = tid / JT_BLK;       // 0 or 1
        const float* Xb = X + ((long)b * C_DIM) * TN + j0 + jl;
        #pragma unroll
        for (int c = 0; c < 64; c += 2) {
            int cc = c + cst;
            float x = Xb[(long)cc * TN];
            unsigned short h, l;
            split2(x, h, l);
            int si = xs_idx(jl, cc);
            Xh[si] = h;
            Xl[si] = l;
        }
    }
    __syncthreads();

    // Warp tiling: 6 warps = 3 (j) x 2 (o); warp tile 32j x 32o
    const int wid = tid >> 5, lane = tid & 31;
    const int wj = wid % 3, wo = wid / 3;
    const int lr = lane >> 2, lc = lane & 3;

    const unsigned* Xh32 = (const unsigned*)Xh;
    const unsigned* Xl32 = (const unsigned*)Xl;
    const unsigned* Wh32 = (const unsigned*)Wh;
    const unsigned* Wl32 = (const unsigned*)Wl;

    float acc[2][4][4] = {};

    #pragma unroll
    for (int k0 = 0; k0 < 64; k0 += 16) {
        unsigned Ah[2][4], Al[2][4];
        #pragma unroll
        for (int mt = 0; mt < 2; mt++) {
            int jb = wj * 32 + mt * 16;
            int r0 = jb + lr, r1 = jb + lr + 8;
            int c0 = k0 + 2 * lc, c1 = k0 + 2 * lc + 8;
            Ah[mt][0] = Xh32[xs_idx(r0, c0) >> 1];
            Ah[mt][1] = Xh32[xs_idx(r1, c0) >> 1];
            Ah[mt][2] = Xh32[xs_idx(r0, c1) >> 1];
            Ah[mt][3] = Xh32[xs_idx(r1, c1) >> 1];
            Al[mt][0] = Xl32[xs_idx(r0, c0) >> 1];
            Al[mt][1] = Xl32[xs_idx(r1, c0) >> 1];
            Al[mt][2] = Xl32[xs_idx(r0, c1) >> 1];
            Al[mt][3] = Xl32[xs_idx(r1, c1) >> 1];
        }
        unsigned Bh[4][2], Bl[4][2];
        #pragma unroll
        for (int nt = 0; nt < 4; nt++) {
            int o = wo * 32 + nt * 8 + lr;
            int c0 = k0 + 2 * lc;
            Bh[nt][0] = Wh32[(o * 72 + c0) >> 1];
            Bh[nt][1] = Wh32[(o * 72 + c0 + 8) >> 1];
            Bl[nt][0] = Wl32[(o * 72 + c0) >> 1];
            Bl[nt][1] = Wl32[(o * 72 + c0 + 8) >> 1];
        }
        #pragma unroll
        for (int mt = 0; mt < 2; mt++) {
            #pragma unroll
            for (int nt = 0; nt < 4; nt++) {
                mma_bf16(acc[mt][nt], Ah[mt], Bh[nt]);  // hi*hi
                mma_bf16(acc[mt][nt], Ah[mt], Bl[nt]);  // hi*lo
                mma_bf16(acc[mt][nt], Al[mt], Bh[nt]);  // lo*hi
            }
        }
    }

    // Epilogue: + bias, store fp32 scratch. Thread holds
    // d0:(j=jb+lr, o=ob), d1:(j, o+1), d2:(j+8, o), d3:(j+8, o+1).
    #pragma unroll
    for (int mt = 0; mt < 2; mt++) {
        #pragma unroll
        for (int nt = 0; nt < 4; nt++) {
            int jb = wj * 32 + mt * 16;
            int ob = wo * 32 + nt * 8 + 2 * lc;
            int r0 = jb + lr, r1 = r0 + 8;
            float b0 = bias_s[ob], b1 = bias_s[ob + 1];
            size_t base0 = ((size_t)b * C_DIM + ob) * TN + j0;
            size_t base1 = base0 + TN;  // ob+1
            O[base0 + r0] = acc[mt][nt][0] + b0;
            O[base1 + r0] = acc[mt][nt][1] + b1;
            O[base0 + r1] = acc[mt][nt][2] + b0;
            O[base1 + r1] = acc[mt][nt][3] + b1;
        }
    }
}

// ---------------- Kernel B: 7-tap sliding-window softmax ----------------
// grid = (8 t-tiles of 16, 64 channels, 8 batches), 256 threads.
// K/V rows [t0-3, t0+19) staged in SMEM (zero-filled at T edges == padding),
// each element reused 7x from SMEM instead of L2.
#define TT 16
__global__ __launch_bounds__(256) void attn_kernel(float* __restrict__ out)
{
    __shared__ float Ks[TT + 6][208];
    __shared__ float Vs[TT + 6][208];

    const int t0 = blockIdx.x * TT;
    const int o  = blockIdx.y;
    const int b  = blockIdx.z;
    const size_t base = ((size_t)b * C_DIM + o) * TN;

    const float* __restrict__ Q = g_proj[0];
    const float* __restrict__ K = g_proj[1];
    const float* __restrict__ V = g_proj[2];

    const int tid = threadIdx.x;

    for (int idx = tid; idx < (TT + 6) * N_DIM; idx += 256) {
        int r = idx / N_DIM;
        int n = idx - r * N_DIM;
        int t = t0 - 3 + r;
        bool ok = (t >= 0) && (t < T_DIM);
        size_t g = base + (size_t)(ok ? t : 0) * N_DIM + n;
        Ks[r][n] = ok ? K[g] : 0.0f;
        Vs[r][n] = ok ? V[g] : 0.0f;
    }
    __syncthreads();

    const int n = tid;
    if (n < N_DIM) {
        #pragma unroll 4
        for (int tl = 0; tl < TT; tl++) {
            int t = t0 + tl;
            float qv = Q[base + (size_t)t * N_DIM + n];

            float s[7], vv[7];
            #pragma unroll
            for (int i = 0; i < 7; i++) {
                s[i]  = qv * Ks[tl + i][n];   // tap offset i-3; OOB => 0 (matches pad)
                vv[i] = Vs[tl + i][n];
            }
            float m = s[0];
            #pragma unroll
            for (int i = 1; i < 7; i++) m = fmaxf(m, s[i]);
            float den = 0.0f, num = 0.0f;
            #pragma unroll
            for (int i = 0; i < 7; i++) {
                float e = __expf(s[i] - m);
                den += e;
                num = fmaf(e, vv[i], num);
            }
            out[base + (size_t)t * N_DIM + n] = num / den;
        }
    }
}

// ---------------- launch ----------------
extern "C" void kernel_launch(void* const* d_in, const int* in_sizes, int n_in,
                              void* d_out, int out_size)
{
    (void)in_sizes; (void)n_in; (void)out_size;
    const float* q  = (const float*)d_in[0];
    const float* k  = (const float*)d_in[1];
    const float* v  = (const float*)d_in[2];
    const float* Wq = (const float*)d_in[3];
    const float* bq = (const float*)d_in[4];
    const float* Wk = (const float*)d_in[5];
    const float* bk = (const float*)d_in[6];
    const float* Wv = (const float*)d_in[7];
    const float* bv = (const float*)d_in[8];

    dim3 gA(NBLK_J, B_DIM, 3);
    proj_kernel<<<gA, 192>>>(q, k, v, Wq, bq, Wk, bk, Wv, bv);

    dim3 gB(T_DIM / TT, C_DIM, B_DIM);
    attn_kernel<<<gB, 256>>>((float*)d_out);
}

// round 3
// speedup vs baseline: 1.3124x; 1.3124x over previous
#include <cuda_runtime.h>
#include <cuda_bf16.h>

// Problem constants
#define B_DIM 8
#define C_DIM 64
#define T_DIM 128
#define N_DIM 207
#define TN    (T_DIM * N_DIM)   // 26496 pixels per (b, channel)
#define JT_BLK 96               // kernel A: pixels per block tile (26496 = 96*276)
#define NBLK_J (TN / JT_BLK)    // 276

// Scratch for projected Q, K, V (fp32). Static __device__ array per harness rules.
__device__ float g_proj[3][(size_t)B_DIM * C_DIM * TN];

// ---------------- helpers ----------------
__device__ __forceinline__ unsigned short bf16_bits(__nv_bfloat16 h) {
    return *reinterpret_cast<unsigned short*>(&h);
}

// Split fp32 into hi/lo bf16 (3-term MMA gives ~2^-16 relative error)
__device__ __forceinline__ void split2(float x, unsigned short& h, unsigned short& l) {
    __nv_bfloat16 hb = __float2bfloat16(x);
    float r = x - __bfloat162float(hb);
    __nv_bfloat16 lb = __float2bfloat16(r);
    h = bf16_bits(hb);
    l = bf16_bits(lb);
}

// Swizzled half-index into the transposed X tile Xs[j][c]:
//  - row stride 72 halves (36 words)
//  - XOR on c bits [1:2] keyed by j bits [3:4]
// => conflict-free for both transposed 16-bit stores (lanes = consecutive j)
//    and m16n8k16 A-fragment loads (lanes = (j=lane/4, c=2*(lane%4))).
__device__ __forceinline__ int xs_idx(int j, int c) {
    return j * 72 + (c ^ (((j >> 3) & 3) << 1));
}

__device__ __forceinline__ void mma_bf16(float* d, const unsigned* a, const unsigned* b) {
    asm volatile(
        "mma.sync.aligned.m16n8k16.row.col.f32.bf16.bf16.f32 "
        "{%0,%1,%2,%3},{%4,%5,%6,%7},{%8,%9},{%0,%1,%2,%3};\n"
        : "+f"(d[0]), "+f"(d[1]), "+f"(d[2]), "+f"(d[3])
        : "r"(a[0]), "r"(a[1]), "r"(a[2]), "r"(a[3]),
          "r"(b[0]), "r"(b[1]));
}

// ---------------- Kernel A: projections via split-bf16 tensor cores ----------------
// grid = (276 j-tiles, 8 batches, 3 projections), 192 threads (6 warps).
// Block computes Y[96 j][64 o] = X[64 c][96 j]^T * W[64 o][64 c]^T + bias
// Epilogue is staged through SMEM so global stores are coalesced float4.
#define YS_STRIDE 100   // fp32 words; conflict-free for fragment writes (bank = lr + 8*lc (+4))
__global__ __launch_bounds__(192) void proj_kernel(
    const float* __restrict__ q, const float* __restrict__ k, const float* __restrict__ v,
    const float* __restrict__ Wq, const float* __restrict__ bq,
    const float* __restrict__ Wk, const float* __restrict__ bk,
    const float* __restrict__ Wv, const float* __restrict__ bv)
{
    // Union: Xh/Xl (staging + MMA A operand) reuse the same bytes as Ysm (epilogue)
    __shared__ __align__(16) char smem_u[JT_BLK * 72 * 2 * sizeof(unsigned short)]; // 27648 B >= 64*100*4
    __shared__ unsigned short Wh[64 * 72], Wl[64 * 72];
    __shared__ float bias_s[64];

    unsigned short* Xh = (unsigned short*)smem_u;
    unsigned short* Xl = Xh + JT_BLK * 72;
    float* Ysm = (float*)smem_u;

    const int z = blockIdx.z;
    const float* __restrict__ X = (z == 0) ? q : (z == 1) ? k : v;
    const float* __restrict__ W = (z == 0) ? Wq : (z == 1) ? Wk : Wv;
    const float* __restrict__ bb = (z == 0) ? bq : (z == 1) ? bk : bv;
    float* __restrict__ O = g_proj[z];

    const int b   = blockIdx.y;
    const long j0 = (long)blockIdx.x * JT_BLK;
    const int tid = threadIdx.x;

    // Weights -> split bf16 SMEM (stride 72: B-fragment reads conflict-free)
    for (int idx = tid; idx < 64 * 64; idx += 192) {
        int o = idx >> 6, c = idx & 63;
        unsigned short h, l;
        split2(W[idx], h, l);
        Wh[o * 72 + c] = h;
        Wl[o * 72 + c] = l;
    }
    if (tid < 64) bias_s[tid] = bb[tid];

    // X tile [64 c][96 j] -> transposed split-bf16 Xs[j][c]
    {
        const int jl  = tid % JT_BLK;       // 0..95
        const int cst = tid / JT_BLK;       // 0 or 1
        const float* Xb = X + ((long)b * C_DIM) * TN + j0 + jl;
        #pragma unroll
        for (int c = 0; c < 64; c += 2) {
            int cc = c + cst;
            float x = Xb[(long)cc * TN];
            unsigned short h, l;
            split2(x, h, l);
            int si = xs_idx(jl, cc);
            Xh[si] = h;
            Xl[si] = l;
        }
    }
    __syncthreads();

    // Warp tiling: 6 warps = 3 (j) x 2 (o); warp tile 32j x 32o
    const int wid = tid >> 5, lane = tid & 31;
    const int wj = wid % 3, wo = wid / 3;
    const int lr = lane >> 2, lc = lane & 3;

    const unsigned* Xh32 = (const unsigned*)Xh;
    const unsigned* Xl32 = (const unsigned*)Xl;
    const unsigned* Wh32 = (const unsigned*)Wh;
    const unsigned* Wl32 = (const unsigned*)Wl;

    float acc[2][4][4] = {};

    #pragma unroll
    for (int k0 = 0; k0 < 64; k0 += 16) {
        unsigned Ah[2][4], Al[2][4];
        #pragma unroll
        for (int mt = 0; mt < 2; mt++) {
            int jb = wj * 32 + mt * 16;
            int r0 = jb + lr, r1 = jb + lr + 8;
            int c0 = k0 + 2 * lc, c1 = k0 + 2 * lc + 8;
            Ah[mt][0] = Xh32[xs_idx(r0, c0) >> 1];
            Ah[mt][1] = Xh32[xs_idx(r1, c0) >> 1];
            Ah[mt][2] = Xh32[xs_idx(r0, c1) >> 1];
            Ah[mt][3] = Xh32[xs_idx(r1, c1) >> 1];
            Al[mt][0] = Xl32[xs_idx(r0, c0) >> 1];
            Al[mt][1] = Xl32[xs_idx(r1, c0) >> 1];
            Al[mt][2] = Xl32[xs_idx(r0, c1) >> 1];
            Al[mt][3] = Xl32[xs_idx(r1, c1) >> 1];
        }
        unsigned Bh[4][2], Bl[4][2];
        #pragma unroll
        for (int nt = 0; nt < 4; nt++) {
            int o = wo * 32 + nt * 8 + lr;
            int c0 = k0 + 2 * lc;
            Bh[nt][0] = Wh32[(o * 72 + c0) >> 1];
            Bh[nt][1] = Wh32[(o * 72 + c0 + 8) >> 1];
            Bl[nt][0] = Wl32[(o * 72 + c0) >> 1];
            Bl[nt][1] = Wl32[(o * 72 + c0 + 8) >> 1];
        }
        #pragma unroll
        for (int mt = 0; mt < 2; mt++) {
            #pragma unroll
            for (int nt = 0; nt < 4; nt++) {
                mma_bf16(acc[mt][nt], Ah[mt], Bh[nt]);  // hi*hi
                mma_bf16(acc[mt][nt], Ah[mt], Bl[nt]);  // hi*lo
                mma_bf16(acc[mt][nt], Al[mt], Bh[nt]);  // lo*hi
            }
        }
    }

    // Epilogue: acc -> SMEM (conflict-free) -> coalesced float4 global stores
    __syncthreads();   // done reading Xh/Xl; safe to overwrite with Ysm
    #pragma unroll
    for (int mt = 0; mt < 2; mt++) {
        #pragma unroll
        for (int nt = 0; nt < 4; nt++) {
            int jb = wj * 32 + mt * 16;
            int ob = wo * 32 + nt * 8 + 2 * lc;
            int r0 = jb + lr, r1 = r0 + 8;
            float b0 = bias_s[ob], b1 = bias_s[ob + 1];
            Ysm[ob * YS_STRIDE + r0]       = acc[mt][nt][0] + b0;
            Ysm[(ob + 1) * YS_STRIDE + r0] = acc[mt][nt][1] + b1;
            Ysm[ob * YS_STRIDE + r1]       = acc[mt][nt][2] + b0;
            Ysm[(ob + 1) * YS_STRIDE + r1] = acc[mt][nt][3] + b1;
        }
    }
    __syncthreads();

    {
        const size_t obase = ((size_t)b * C_DIM) * TN + j0;
        if (lane < 24) {
            #pragma unroll
            for (int o = wid; o < 64; o += 6) {   // 6 warps cover 64 rows
                float4 val = *(const float4*)&Ysm[o * YS_STRIDE + 4 * lane];
                *(float4*)&O[obase + (size_t)o * TN + 4 * lane] = val;
            }
        }
    }
}

// ---------------- Kernel B: 7-tap sliding-window softmax ----------------
// grid = (8 t-tiles of 16, 64 channels, 8 batches), 256 threads.
// K/V rows [t0-3, t0+19) staged in SMEM; compute has 2-row ILP per lane
// and pre-scaled log2e scores (exp2f, no extra mul).
#define TT 16
__global__ __launch_bounds__(256) void attn_kernel(float* __restrict__ out)
{
    __shared__ float Ks[TT + 6][208];
    __shared__ float Vs[TT + 6][208];

    const int t0 = blockIdx.x * TT;
    const int o  = blockIdx.y;
    const int b  = blockIdx.z;
    const size_t base = ((size_t)b * C_DIM + o) * TN;

    const float* __restrict__ Q = g_proj[0];
    const float* __restrict__ K = g_proj[1];
    const float* __restrict__ V = g_proj[2];

    const int tid = threadIdx.x;

    // Staging: row loop, no integer division, high MLP
    if (tid < N_DIM) {
        #pragma unroll
        for (int r = 0; r < TT + 6; r++) {
            int t = t0 - 3 + r;
            bool ok = ((unsigned)t < (unsigned)T_DIM);
            size_t g = base + (size_t)(ok ? t : 0) * N_DIM + tid;
            Ks[r][tid] = ok ? K[g] : 0.0f;
            Vs[r][tid] = ok ? V[g] : 0.0f;
        }
    }
    __syncthreads();

    if (tid < N_DIM) {
        const int n = tid;
        const float* qp = Q + base + (size_t)t0 * N_DIM + n;
        float* op = out + base + (size_t)t0 * N_DIM + n;
        const float L2E = 1.44269504088896f;

        #pragma unroll
        for (int tl = 0; tl < TT / 2; tl++) {
            // Two independent rows (tl, tl+8) per iteration for ILP
            float q0 = qp[tl * N_DIM] * L2E;
            float q1 = qp[(tl + 8) * N_DIM] * L2E;

            float s0[7], s1[7], v0[7], v1[7];
            #pragma unroll
            for (int i = 0; i < 7; i++) {
                s0[i] = q0 * Ks[tl + i][n];
                v0[i] = Vs[tl + i][n];
                s1[i] = q1 * Ks[tl + 8 + i][n];
                v1[i] = Vs[tl + 8 + i][n];
            }
            float m0 = s0[0], m1 = s1[0];
            #pragma unroll
            for (int i = 1; i < 7; i++) { m0 = fmaxf(m0, s0[i]); m1 = fmaxf(m1, s1[i]); }
            float den0 = 0.f, num0 = 0.f, den1 = 0.f, num1 = 0.f;
            #pragma unroll
            for (int i = 0; i < 7; i++) {
                float e0 = exp2f(s0[i] - m0);
                float e1 = exp2f(s1[i] - m1);
                den0 += e0; num0 = fmaf(e0, v0[i], num0);
                den1 += e1; num1 = fmaf(e1, v1[i], num1);
            }
            op[tl * N_DIM]       = __fdividef(num0, den0);
            op[(tl + 8) * N_DIM] = __fdividef(num1, den1);
        }
    }
}

// ---------------- launch ----------------
extern "C" void kernel_launch(void* const* d_in, const int* in_sizes, int n_in,
                              void* d_out, int out_size)
{
    (void)in_sizes; (void)n_in; (void)out_size;
    const float* q  = (const float*)d_in[0];
    const float* k  = (const float*)d_in[1];
    const float* v  = (const float*)d_in[2];
    const float* Wq = (const float*)d_in[3];
    const float* bq = (const float*)d_in[4];
    const float* Wk = (const float*)d_in[5];
    const float* bk = (const float*)d_in[6];
    const float* Wv = (const float*)d_in[7];
    const float* bv = (const float*)d_in[8];

    dim3 gA(NBLK_J, B_DIM, 3);
    proj_kernel<<<gA, 192>>>(q, k, v, Wq, bq, Wk, bk, Wv, bv);

    dim3 gB(T_DIM / TT, C_DIM, B_DIM);
    attn_kernel<<<gB, 256>>>((float*)d_out);
}